// round 12
// baseline (speedup 1.0000x reference)
#include <cuda_runtime.h>
#include <cuda_bf16.h>

// Problem constants:
//   N_B=16, N_T=48, P=10000, modes [0,1],[1,-1],[1,0],[1,1]; params row = 2688 floats.
// Output concat (float32):
//   kappa (16,1,10000,48) | m (16,2,10000,48) | H (16,2,2,10000,48) | tau (16,1,10000,48)
//   = 245.76 MB pure writes; steady-state wall ~6.25 TB/s (write ceiling).
//
// R12 = R9 structure with half-size blocks: 240 threads, 20 p per block,
// 8000 blocks, launch_bounds(240,8) (same 1920 threads/SM). Tests the
// "more, shorter blocks" direction implied by the R10 regression.

#define NB   16
#define NT   48
#define PN   10000
#define SZ   480000           // 10000 * 48
#define ROW  2688

#define TPB    240            // threads per block
#define PTILE  20             // p per block = TPB/12

// Padded smem layout: logical i lives at i + (i>>5)  (stride-33 per 32-block).
#define PAD(i) ((i) + ((i) >> 5))
// Hot-loop offsets: logical index = 32*tg + r, r = 8j+8+c in [8,43].
// Physical = 33*tg + r + (r>>5): base 33*tg at runtime, OFF(j,c) compile-time.
#define OFF(j,c) ((8*(j)+8+(c)) + ((8*(j)+8+(c)) >> 5))

__device__ __forceinline__ float softplus_fast(float x) {
    // max(x,0) + log(1+exp(-|x|)) via MUFU (EX2/LG2). rel err ~2^-21 << 1e-3 budget.
    float e = __expf(-fabsf(x));
    return fmaxf(x, 0.0f) + __logf(1.0f + e);
}

__device__ __forceinline__ void st4cs(float* dst, float a, float b, float c, float d) {
    __stcs(reinterpret_cast<float4*>(dst), make_float4(a, b, c, d));
}

__global__ __launch_bounds__(TPB, 8)
void decode_param_cnn_fourier_kernel(const float* __restrict__ params,
                                     float* __restrict__ out) {
    __shared__ float pp[PAD(447) + 1];     // padded params row
    __shared__ float Ssh[PTILE * 8];       // per-p: S0..S5, c0, s0
    __shared__ float gb[2];                // gamma, beta

    const int tid = threadIdx.x;
    const int b   = blockIdx.y;
    for (int i = tid; i < 448; i += TPB)
        pp[PAD(i)] = params[(size_t)b * ROW + i];
    __syncthreads();

    const float w = 0.06283185307179586f;   // 2*pi/100

    // Per-p precompute: 20 p-slots * 6 fields = 120 entries.
    if (tid < PTILE * 6) {
        const int pl = tid / 6, f = tid - pl * 6;
        const int p2 = blockIdx.x * PTILE + pl;
        const int gx = p2 / 100, gy = p2 - gx * 100;
        int m1 = gx - gy; if (m1 < 0)    m1 += 100;
        int m3 = gx + gy; if (m3 >= 100) m3 -= 100;
        float c1, s1, c2, s2, c3, s3;
        __sincosf(w * (float)m1, &s1, &c1);   // mode [1,-1]
        __sincosf(w * (float)gx, &s2, &c2);   // mode [1,0]
        __sincosf(w * (float)m3, &s3, &c3);   // mode [1,1]
        float acc = pp[PAD(46 + f)];          // constant offset term
        acc = fmaf(pp[PAD( 8 + 2 * f)], c1, acc);
        acc = fmaf(pp[PAD( 9 + 2 * f)], s1, acc);
        acc = fmaf(pp[PAD(40 + 2 * f)], c2, acc);
        acc = fmaf(pp[PAD(41 + 2 * f)], s2, acc);
        acc = fmaf(pp[PAD(52 + 2 * f)], c3, acc);
        acc = fmaf(pp[PAD(53 + 2 * f)], s3, acc);
        Ssh[pl * 8 + f] = acc;
        if (f == 0) {
            float c0, s0;
            __sincosf(w * (float)gy, &s0, &c0);   // mode [0,1]
            Ssh[pl * 8 + 6] = c0;
            Ssh[pl * 8 + 7] = s0;
        }
    }
    if (tid == PTILE * 6) {
        gb[0] = softplus_fast(pp[PAD(44)]);
        gb[1] = softplus_fast(pp[PAD(45)]);
    }
    __syncthreads();

    // Main: thread = (p-local, t-group of 4). Linear tid -> contiguous warp stores.
    const int tg = tid % 12;
    const int pl = tid / 12;
    const int p  = blockIdx.x * PTILE + pl;

    // Padded base for this thread's coeff window; all loads use immediate offsets.
    const float* __restrict__ q = pp + 33 * tg;

    const float S0 = Ssh[pl * 8 + 0], S1 = Ssh[pl * 8 + 1], S2 = Ssh[pl * 8 + 2];
    const float S3 = Ssh[pl * 8 + 3], S4 = Ssh[pl * 8 + 4], S5 = Ssh[pl * 8 + 5];
    const float c0 = Ssh[pl * 8 + 6], s0 = Ssh[pl * 8 + 7];
    const float gamma = gb[0], beta = gb[1];

    float kv[4], m1v[4], m2v[4], h00v[4], h01v[4], h11v[4], tv[4];

#pragma unroll
    for (int j = 0; j < 4; j++) {
        const float f0 = fmaf(q[OFF(j, 0)],  c0, fmaf(q[OFF(j, 1)],  s0, S0));
        const float f1 = fmaf(q[OFF(j, 2)],  c0, fmaf(q[OFF(j, 3)],  s0, S1));
        const float f2 = fmaf(q[OFF(j, 4)],  c0, fmaf(q[OFF(j, 5)],  s0, S2));
        const float vx = fmaf(q[OFF(j, 6)],  c0, fmaf(q[OFF(j, 7)],  s0, S3));
        const float vy = fmaf(q[OFF(j, 8)],  c0, fmaf(q[OFF(j, 9)],  s0, S4));
        const float f5 = fmaf(q[OFF(j, 10)], c0, fmaf(q[OFF(j, 11)], s0, S5));

        kv[j]  = softplus_fast(f0);
        m1v[j] = f1;
        m2v[j] = f2;
        const float bvx = beta * vx;
        h00v[j] = fmaf(bvx, vx, gamma);
        h01v[j] = bvx * vy;
        h11v[j] = fmaf(beta * vy, vy, gamma);
        tv[j]  = softplus_fast(f5);
    }

    const size_t base = (size_t)p * NT + (size_t)(tg * 4);   // 16B-aligned

    st4cs(out + (size_t)b * SZ                + base, kv[0],  kv[1],  kv[2],  kv[3]);
    st4cs(out + (size_t)(16 + 2 * b + 0) * SZ + base, m1v[0], m1v[1], m1v[2], m1v[3]);
    st4cs(out + (size_t)(16 + 2 * b + 1) * SZ + base, m2v[0], m2v[1], m2v[2], m2v[3]);
    st4cs(out + (size_t)(48 + 4 * b + 0) * SZ + base, h00v[0], h00v[1], h00v[2], h00v[3]);
    st4cs(out + (size_t)(48 + 4 * b + 1) * SZ + base, h01v[0], h01v[1], h01v[2], h01v[3]);
    st4cs(out + (size_t)(48 + 4 * b + 2) * SZ + base, h01v[0], h01v[1], h01v[2], h01v[3]);
    st4cs(out + (size_t)(48 + 4 * b + 3) * SZ + base, h11v[0], h11v[1], h11v[2], h11v[3]);
    st4cs(out + (size_t)(112 + b) * SZ        + base, tv[0],  tv[1],  tv[2],  tv[3]);
}

extern "C" void kernel_launch(void* const* d_in, const int* in_sizes, int n_in,
                              void* d_out, int out_size) {
    const float* params = (const float*)d_in[0];
    float* out = (float*)d_out;
    dim3 grid(PN / PTILE, NB, 1);   // 500 x 16 = 8000 blocks
    dim3 block(TPB, 1, 1);
    decode_param_cnn_fourier_kernel<<<grid, block>>>(params, out);
}

// round 13
// speedup vs baseline: 1.0073x; 1.0073x over previous
#include <cuda_runtime.h>
#include <cuda_bf16.h>

// decode_param_CNN_Fourier — final kernel (sm_100a / B200).
//
// Problem:
//   N_B=16, N_T=48, P=10000, modes [0,1],[1,-1],[1,0],[1,1]; params row = 2688 floats.
// Output concat (float32):
//   kappa (16,1,10000,48) | m (16,2,10000,48) | H (16,2,2,10000,48) | tau (16,1,10000,48)
//   = 245.76 MB pure writes.
//
// Performance summary (campaign):
//   84.0us  baseline (12-way smem bank conflicts on coeff reads, L1 @ 90%)
//   45.0us  +stride-33 padded smem (conflict-free)
//   39.2us  +hoisted index math (compile-time offsets), per-p S/trig smem
//           precompute, MUFU softplus, .cs streaming stores
//   39.2-39.5us across 6 configs varying occupancy 40-89%, LDS volume 2.8x,
//           cache policy, and block granularity -> pinned at the pure-write
//           HBM ceiling: 245.76 MB / 39.3 us = ~6.25 TB/s (~78% of spec).
//
// Config: 480 threads, 40 p per block, 4000 blocks, launch_bounds(480,4)
// (regs 32, occ ~80%). Warp lane = (p-local, t-group): every store is a
// contiguous 512B run per warp in all 8 output regions.

#define NB   16
#define NT   48
#define SZ   480000           // 10000 * 48
#define ROW  2688

// Padded smem layout: logical i lives at i + (i>>5)  (stride-33 per 32-block).
// Coeff reads at base s = 8t+8 are stride-32-float across the warp's 12 tg
// values -> single bank unpadded (12-way conflict); stride-33 -> 12 distinct banks.
#define PAD(i) ((i) + ((i) >> 5))
// Hot-loop offsets: logical index = 32*tg + r, r = 8j+8+c in [8,43].
// Physical = 33*tg + r + (r>>5): base 33*tg at runtime, OFF(j,c) compile-time.
#define OFF(j,c) ((8*(j)+8+(c)) + ((8*(j)+8+(c)) >> 5))

__device__ __forceinline__ float softplus_fast(float x) {
    // max(x,0) + log(1+exp(-|x|)) via MUFU (EX2/LG2). rel err ~2^-21 << 1e-3 budget.
    float e = __expf(-fabsf(x));
    return fmaxf(x, 0.0f) + __logf(1.0f + e);
}

__device__ __forceinline__ void st4cs(float* dst, float a, float b, float c, float d) {
    __stcs(reinterpret_cast<float4*>(dst), make_float4(a, b, c, d));
}

__global__ __launch_bounds__(480, 4)
void decode_param_cnn_fourier_kernel(const float* __restrict__ params,
                                     float* __restrict__ out) {
    __shared__ float pp[PAD(447) + 1];   // padded params row
    __shared__ float Ssh[40 * 8];        // per-p: S0..S5, c0, s0
    __shared__ float gb[2];              // gamma, beta

    const int tid = threadIdx.x;
    const int b   = blockIdx.y;
    if (tid < 448) pp[PAD(tid)] = params[(size_t)b * ROW + tid];
    __syncthreads();

    const float w = 0.06283185307179586f;   // 2*pi/100

    // Per-(b,p) precompute: block covers p in [40*blockIdx.x, +40).
    // (pl, f) thread pairs compute the t-independent field sums S (modes
    // [1,-1],[1,0],[1,1] + constant offsets); f==0 also writes mode-0 trig.
    if (tid < 240) {
        const int pl = tid / 6, f = tid - pl * 6;
        const int p2 = blockIdx.x * 40 + pl;
        const int gx = p2 / 100, gy = p2 - gx * 100;
        int m1 = gx - gy; if (m1 < 0)    m1 += 100;
        int m3 = gx + gy; if (m3 >= 100) m3 -= 100;
        float c1, s1, c2, s2, c3, s3;
        __sincosf(w * (float)m1, &s1, &c1);   // mode [1,-1]
        __sincosf(w * (float)gx, &s2, &c2);   // mode [1,0]
        __sincosf(w * (float)m3, &s3, &c3);   // mode [1,1]
        float acc = pp[PAD(46 + f)];          // constant offset term
        acc = fmaf(pp[PAD( 8 + 2 * f)], c1, acc);
        acc = fmaf(pp[PAD( 9 + 2 * f)], s1, acc);
        acc = fmaf(pp[PAD(40 + 2 * f)], c2, acc);
        acc = fmaf(pp[PAD(41 + 2 * f)], s2, acc);
        acc = fmaf(pp[PAD(52 + 2 * f)], c3, acc);
        acc = fmaf(pp[PAD(53 + 2 * f)], s3, acc);
        Ssh[pl * 8 + f] = acc;
        if (f == 0) {
            float c0, s0;
            __sincosf(w * (float)gy, &s0, &c0);   // mode [0,1]
            Ssh[pl * 8 + 6] = c0;
            Ssh[pl * 8 + 7] = s0;
        }
    }
    if (tid == 240) {
        gb[0] = softplus_fast(pp[PAD(44)]);
        gb[1] = softplus_fast(pp[PAD(45)]);
    }
    __syncthreads();

    // Main: thread = (p-local, t-group of 4). Linear tid -> contiguous warp stores.
    const int tg = tid % 12;
    const int pl = tid / 12;
    const int p  = blockIdx.x * 40 + pl;

    // Padded base for this thread's coeff window; all loads use immediate offsets.
    const float* __restrict__ q = pp + 33 * tg;

    const float S0 = Ssh[pl * 8 + 0], S1 = Ssh[pl * 8 + 1], S2 = Ssh[pl * 8 + 2];
    const float S3 = Ssh[pl * 8 + 3], S4 = Ssh[pl * 8 + 4], S5 = Ssh[pl * 8 + 5];
    const float c0 = Ssh[pl * 8 + 6], s0 = Ssh[pl * 8 + 7];
    const float gamma = gb[0], beta = gb[1];

    float kv[4], m1v[4], m2v[4], h00v[4], h01v[4], h11v[4], tv[4];

#pragma unroll
    for (int j = 0; j < 4; j++) {
        const float f0 = fmaf(q[OFF(j, 0)],  c0, fmaf(q[OFF(j, 1)],  s0, S0));
        const float f1 = fmaf(q[OFF(j, 2)],  c0, fmaf(q[OFF(j, 3)],  s0, S1));
        const float f2 = fmaf(q[OFF(j, 4)],  c0, fmaf(q[OFF(j, 5)],  s0, S2));
        const float vx = fmaf(q[OFF(j, 6)],  c0, fmaf(q[OFF(j, 7)],  s0, S3));
        const float vy = fmaf(q[OFF(j, 8)],  c0, fmaf(q[OFF(j, 9)],  s0, S4));
        const float f5 = fmaf(q[OFF(j, 10)], c0, fmaf(q[OFF(j, 11)], s0, S5));

        kv[j]  = softplus_fast(f0);
        m1v[j] = f1;
        m2v[j] = f2;
        const float bvx = beta * vx;
        h00v[j] = fmaf(bvx, vx, gamma);
        h01v[j] = bvx * vy;
        h11v[j] = fmaf(beta * vy, vy, gamma);
        tv[j]  = softplus_fast(f5);
    }

    const size_t base = (size_t)p * NT + (size_t)(tg * 4);   // 16B-aligned

    st4cs(out + (size_t)b * SZ                + base, kv[0],  kv[1],  kv[2],  kv[3]);
    st4cs(out + (size_t)(16 + 2 * b + 0) * SZ + base, m1v[0], m1v[1], m1v[2], m1v[3]);
    st4cs(out + (size_t)(16 + 2 * b + 1) * SZ + base, m2v[0], m2v[1], m2v[2], m2v[3]);
    st4cs(out + (size_t)(48 + 4 * b + 0) * SZ + base, h00v[0], h00v[1], h00v[2], h00v[3]);
    st4cs(out + (size_t)(48 + 4 * b + 1) * SZ + base, h01v[0], h01v[1], h01v[2], h01v[3]);
    st4cs(out + (size_t)(48 + 4 * b + 2) * SZ + base, h01v[0], h01v[1], h01v[2], h01v[3]);
    st4cs(out + (size_t)(48 + 4 * b + 3) * SZ + base, h11v[0], h11v[1], h11v[2], h11v[3]);
    st4cs(out + (size_t)(112 + b) * SZ        + base, tv[0],  tv[1],  tv[2],  tv[3]);
}

extern "C" void kernel_launch(void* const* d_in, const int* in_sizes, int n_in,
                              void* d_out, int out_size) {
    const float* params = (const float*)d_in[0];
    float* out = (float*)d_out;
    dim3 grid(250, NB, 1);
    dim3 block(480, 1, 1);
    decode_param_cnn_fourier_kernel<<<grid, block>>>(params, out);
}